// round 8
// baseline (speedup 1.0000x reference)
#include <cuda_runtime.h>

// Problem constants (from reference): B=1024, C=200, L=3, DIM=512
#define BATCH 1024
#define CCH   200
#define ROWS  201          // C + 1 (cls row prepended)
#define DIMV  512
#define BPB   16           // batches (output rows along b) per block

// out[b, 0, d]   = cls[d] + pe[0, d]
// out[b, c+1, d] = x[b,max(c-1,0)]*W[c,0,d] + x[b,c]*W[c,1,d]
//                + x[b,min(c+1,199)]*W[c,2,d] + pe[c+1, d]
__global__ __launch_bounds__(128, 8)
void gse_kernel(const float* __restrict__ x,     // [1024, 200]
                const float* __restrict__ W,     // [200, 3, 512]
                const float* __restrict__ cls,   // [512]
                const float* __restrict__ pe,    // [201, 512]
                float* __restrict__ out)         // [1024, 201, 512]
{
    const int cp = blockIdx.x;            // output row index 0..200
    const int b0 = blockIdx.y * BPB;      // base batch for this block
    const int d  = threadIdx.x << 2;      // float4 column 0..508

    // pe for this row, loaded once per block
    const float4 peV = *reinterpret_cast<const float4*>(pe + (size_t)cp * DIMV + d);

    const size_t rowStride = (size_t)ROWS * DIMV;   // stride between batches in out

    if (cp == 0) {
        // cls row: batch-invariant value
        const float4 cv = *reinterpret_cast<const float4*>(cls + d);
        float4 o;
        o.x = cv.x + peV.x; o.y = cv.y + peV.y;
        o.z = cv.z + peV.z; o.w = cv.w + peV.w;
        float* ob = out + (size_t)b0 * rowStride + d;   // cp = 0 offset
        #pragma unroll
        for (int i = 0; i < BPB; ++i) {
            *reinterpret_cast<float4*>(ob) = o;
            ob += rowStride;
        }
        return;
    }

    const int c  = cp - 1;                 // channel index 0..199
    const int i0 = (c > 0) ? (c - 1) : 0;               // edge clamp left
    const int i2 = (c < CCH - 1) ? (c + 1) : (CCH - 1); // edge clamp right

    // W taps for this (c, d) — loaded once per block, reused for 16 batches
    const float* Wc = W + (size_t)c * 3 * DIMV + d;
    const float4 w0 = *reinterpret_cast<const float4*>(Wc);
    const float4 w1 = *reinterpret_cast<const float4*>(Wc + DIMV);
    const float4 w2 = *reinterpret_cast<const float4*>(Wc + 2 * DIMV);

    const float* xb = x + (size_t)b0 * CCH;
    float* ob = out + (size_t)b0 * rowStride + (size_t)cp * DIMV + d;

    #pragma unroll
    for (int i = 0; i < BPB; ++i) {
        // warp-uniform broadcast loads (L1/L2-resident after first touch)
        const float a0 = __ldg(xb + i0);
        const float a1 = __ldg(xb + c);
        const float a2 = __ldg(xb + i2);

        float4 o;
        o.x = fmaf(a0, w0.x, fmaf(a1, w1.x, fmaf(a2, w2.x, peV.x)));
        o.y = fmaf(a0, w0.y, fmaf(a1, w1.y, fmaf(a2, w2.y, peV.y)));
        o.z = fmaf(a0, w0.z, fmaf(a1, w1.z, fmaf(a2, w2.z, peV.z)));
        o.w = fmaf(a0, w0.w, fmaf(a1, w1.w, fmaf(a2, w2.w, peV.w)));

        *reinterpret_cast<float4*>(ob) = o;

        xb += CCH;
        ob += rowStride;
    }
}

extern "C" void kernel_launch(void* const* d_in, const int* in_sizes, int n_in,
                              void* d_out, int out_size) {
    const float* x   = (const float*)d_in[0];   // 1024*200
    const float* W   = (const float*)d_in[1];   // 200*3*512
    const float* cls = (const float*)d_in[2];   // 512
    const float* pe  = (const float*)d_in[3];   // 201*512
    float* out = (float*)d_out;                 // 1024*201*512

    dim3 grid(ROWS, BATCH / BPB);   // (201, 64) — x walks rows for wave-spread
    dim3 block(DIMV / 4);           // 128 threads, one float4 column each
    gse_kernel<<<grid, block>>>(x, W, cls, pe, out);
}